// round 4
// baseline (speedup 1.0000x reference)
#include <cuda_runtime.h>

// Fixed problem shapes: B=4, L=80000, N=512, F=257, STRIDE=256 -> T=311
#define NB  4
#define NL  80000
#define NN  512
#define NF  257
#define NT  311
#define BFT (NB * NF * NT)   // 319708

// Scratch (allocation-free per harness rules)
__device__ float g_frames[NT];
__device__ float g_tcos[NN];
__device__ float g_tsin[NN];
__device__ float g_wl;

// ---------------------------------------------------------------------------
// Prep: clip scalars, serial cumsum for frame positions, accurate base
// twiddles e^{-2*pi*i*k/512} in double.
// ---------------------------------------------------------------------------
__global__ void prep_kernel(const float* __restrict__ win_length,
                            const float* __restrict__ strides) {
    int tid = threadIdx.x;
    if (tid == 0) {
        float wl = fminf(fmaxf(win_length[0], 25.6f), 512.0f);   // WIN_MIN=N/20, WIN_MAX=N
        g_wl = wl;
        float st = fminf(fmaxf(strides[0], 0.0f), 512.0f);        // STRIDE_MIN/MAX
        float acc = 0.0f;
        g_frames[0] = 0.0f;
        for (int t = 1; t < NT; ++t) { acc += st; g_frames[t] = acc; }
    }
    for (int k = tid; k < NN; k += blockDim.x) {
        double ang = -6.283185307179586476925286766559 * (double)k / 512.0;
        g_tcos[k] = (float)cos(ang);
        g_tsin[k] = (float)sin(ang);
    }
}

// ---------------------------------------------------------------------------
// Main: one block per (t, b) frame. 256 threads.
//  Phase 1: windowed samples g[n], g[n+256]; fold u=g0+g1 (even f), v=g0-g1
//           (odd f) into shared.
//  Phase 2: thread f in [0,256) runs the 256-point folded DFT with a register
//           twiddle rotation. f=256 (twiddle (-1)^n over u) comes from a
//           cheap block reduction.
// Output layout (established rounds 1-3):
//   floats [0, BFT)       : spec = |stft| + eps
//   floats [BFT, 2*BFT)   : real(stft)   (harness casts complex64 -> float32)
// ---------------------------------------------------------------------------
__global__ void __launch_bounds__(256)
adstft_kernel(const float* __restrict__ x, float* __restrict__ out) {
    __shared__ float suv[2][256];
    __shared__ float sred[8];

    const int t   = blockIdx.x;
    const int b   = blockIdx.y;
    const int tid = threadIdx.x;

    const float wl    = g_wl;
    const float frame = g_frames[t];
    const float flo   = floorf(frame);
    const float frac  = frame - flo;
    const int   i0    = (int)flo;
    const float hi    = ceilf ((511.0f + wl) * 0.5f);
    const float lo    = floorf((511.0f - wl) * 0.5f);
    const float woff  = (wl - 511.0f) * 0.5f;
    const float* xb   = x + (size_t)b * NL;

    // Phase 1: windowed samples + fold
    float gpair[2];
#pragma unroll
    for (int h = 0; h < 2; ++h) {
        const int n   = tid + h * 256;
        const int idx = i0 + n;
        float v = (idx >= 0 && idx < NL) ? xb[idx] : 0.0f;
        const float base = (float)n - frac;
        float tap = 0.0f;
        if (!(base >= hi || base <= lo)) {
            float ang = 6.2831853071795864f * (base + woff) / wl;
            tap = (0.5f - 0.5f * cosf(ang)) * 0.00390625f;   // / N * 2 = 2/512
        }
        gpair[h] = v * tap;
    }
    const float u = gpair[0] + gpair[1];
    suv[0][tid] = u;                    // even f
    suv[1][tid] = gpair[0] - gpair[1];  // odd f

    // f = 256 partial: sum u[n] * (-1)^n (warp shfl reduce, leaders -> shared)
    float p = (tid & 1) ? -u : u;
#pragma unroll
    for (int o = 16; o > 0; o >>= 1)
        p += __shfl_xor_sync(0xffffffffu, p, o);
    if ((tid & 31) == 0) sred[tid >> 5] = p;
    __syncthreads();

    // Phase 2: per-frequency folded DFT (f = tid)
    {
        const int f = tid;
        const float* hh = suv[f & 1];
        const float wr = g_tcos[f];
        const float wi = g_tsin[f];
        float cr = 1.0f, ci = 0.0f;     // running twiddle e^{-2*pi*i*f*n/512}
        float ar = 0.0f, ai = 0.0f;
#pragma unroll 8
        for (int n = 0; n < 256; ++n) {
            const float gv = hh[n];
            ar = fmaf(gv, cr, ar);
            ai = fmaf(gv, ci, ai);
            const float nr = fmaf(cr, wr, -ci * wi);
            ci = fmaf(ci, wr, cr * wi);
            cr = nr;
        }

        // fractional-shift phase: e^{+i * 2*pi*frac*f/512}
        const float phi = 6.2831853071795864f * frac * (float)f * (1.0f / 512.0f);
        float sp, cp;
        sincosf(phi, &sp, &cp);
        const float re = fmaf(ar, cp, -ai * sp);
        const float im = fmaf(ar, sp,  ai * cp);

        const size_t o = ((size_t)b * NF + f) * NT + t;
        out[o]       = sqrtf(fmaf(re, re, im * im)) + 1.1920929e-7f;  // spec
        out[BFT + o] = re;                                            // real(stft)
    }

    // f = 256 final (thread 0): purely real pre-shift
    if (tid == 0) {
        float ar = 0.0f;
#pragma unroll
        for (int w = 0; w < 8; ++w) ar += sred[w];
        const float phi = 3.1415926535897932f * frac;   // 2*pi*frac*256/512
        float sp, cp;
        sincosf(phi, &sp, &cp);
        const float re = ar * cp;
        const float im = ar * sp;
        const size_t o = ((size_t)b * NF + 256) * NT + t;
        out[o]       = sqrtf(fmaf(re, re, im * im)) + 1.1920929e-7f;
        out[BFT + o] = re;
    }
}

// ---------------------------------------------------------------------------
extern "C" void kernel_launch(void* const* d_in, const int* in_sizes, int n_in,
                              void* d_out, int out_size) {
    // x is the unique large input; win_length is the middle input under both
    // insertion and alphabetical order; strides is the remaining small one.
    int ix = 0;
    for (int i = 1; i < n_in; ++i)
        if (in_sizes[i] > in_sizes[ix]) ix = i;
    const float* x  = (const float*)d_in[ix];
    const float* wl = (const float*)d_in[1];
    const float* st = (const float*)d_in[(ix == 0) ? 2 : 0];
    float* out = (float*)d_out;

    prep_kernel<<<1, 256>>>(wl, st);

    dim3 grid(NT, NB);
    adstft_kernel<<<grid, 256>>>(x, out);
}

// round 5
// speedup vs baseline: 1.3516x; 1.3516x over previous
#include <cuda_runtime.h>

// Fixed problem shapes: B=4, L=80000, N=512, F=257, STRIDE=256 -> T=311
#define NB  4
#define NL  80000
#define NN  512
#define NF  257
#define NT  311
#define BFT (NB * NF * NT)   // 319708

// Scratch (allocation-free per harness rules)
__device__ float g_frames[NT];
__device__ float g_tcos[NN];
__device__ float g_tsin[NN];
__device__ float g_wl;

// ---------------------------------------------------------------------------
// Prep: clip scalars, serial cumsum (matches jnp float accumulation order),
// accurate base twiddles e^{-2*pi*i*k/512} in double.
// ---------------------------------------------------------------------------
__global__ void prep_kernel(const float* __restrict__ win_length,
                            const float* __restrict__ strides) {
    int tid = threadIdx.x;
    if (tid == 0) {
        float wl = fminf(fmaxf(win_length[0], 25.6f), 512.0f);   // WIN_MIN=N/20, WIN_MAX=N
        g_wl = wl;
        float st = fminf(fmaxf(strides[0], 0.0f), 512.0f);        // STRIDE_MIN/MAX
        float acc = 0.0f;
        g_frames[0] = 0.0f;
        for (int t = 1; t < NT; ++t) { acc += st; g_frames[t] = acc; }
    }
    for (int k = tid; k < NN; k += blockDim.x) {
        double ang = -6.283185307179586476925286766559 * (double)k / 512.0;
        g_tcos[k] = (float)cos(ang);
        g_tsin[k] = (float)sin(ang);
    }
}

// ---------------------------------------------------------------------------
// Main: grid (NT, 2), 128 threads. Block (t, half) computes frequencies
// f = half*128 + tid for frame t, ALL 4 batches per thread (batch-folded:
// one twiddle rotation feeds 4 accumulator pairs).
//  Phase 1: windowed samples for 4 batches; radix-2 fold u/v into shared
//           laid out [parity][n][batch] so the main loop reads one float4.
//  Phase 2: 256-iter folded DFT, register twiddle rotation shared across
//           batches. half==1 also computes f=256 via per-batch reductions.
// Output layout: floats [0,BFT) = spec; [BFT,2*BFT) = real(stft).
// ---------------------------------------------------------------------------
__global__ void __launch_bounds__(128)
adstft_kernel(const float* __restrict__ x, float* __restrict__ out) {
    __shared__ float suv[2][256][NB];   // 8 KB

    const int t    = blockIdx.x;
    const int half = blockIdx.y;
    const int tid  = threadIdx.x;

    const float wl    = g_wl;
    const float frame = g_frames[t];
    const float flo   = floorf(frame);
    const float frac  = frame - flo;
    const int   i0    = (int)flo;
    const float hi    = ceilf ((511.0f + wl) * 0.5f);
    const float lo    = floorf((511.0f - wl) * 0.5f);
    const float woff  = (wl - 511.0f) * 0.5f;

    // Phase 1: window taps (shared across batches) + per-batch samples + fold
    float tap[4];
#pragma unroll
    for (int h = 0; h < 4; ++h) {
        const int n = tid + h * 128;
        const float base = (float)n - frac;
        float tp = 0.0f;
        if (!(base >= hi || base <= lo)) {
            float ang = 6.2831853071795864f * (base + woff) / wl;
            tp = (0.5f - 0.5f * __cosf(ang)) * 0.00390625f;   // / N * 2
        }
        tap[h] = tp;
    }
#pragma unroll
    for (int b = 0; b < NB; ++b) {
        const float* xb = x + (size_t)b * NL;
        float g[4];
#pragma unroll
        for (int h = 0; h < 4; ++h) {
            const int idx = i0 + tid + h * 128;
            float v = (idx >= 0 && idx < NL) ? xb[idx] : 0.0f;
            g[h] = v * tap[h];
        }
        suv[0][tid      ][b] = g[0] + g[2];   // u (even f)
        suv[0][tid + 128][b] = g[1] + g[3];
        suv[1][tid      ][b] = g[0] - g[2];   // v (odd f)
        suv[1][tid + 128][b] = g[1] - g[3];
    }
    __syncthreads();

    // Phase 2: folded DFT, f = half*128 + tid, 4 batches per thread
    const int f = (half << 7) + tid;
    const float4* hh = (const float4*)&suv[f & 1][0][0];
    const float wr = g_tcos[f];
    const float wi = g_tsin[f];
    float cr = 1.0f, ci = 0.0f;   // running twiddle e^{-2*pi*i*f*n/512}
    float ar0 = 0.f, ai0 = 0.f, ar1 = 0.f, ai1 = 0.f;
    float ar2 = 0.f, ai2 = 0.f, ar3 = 0.f, ai3 = 0.f;
#pragma unroll 8
    for (int n = 0; n < 256; ++n) {
        const float4 gv = hh[n];
        ar0 = fmaf(gv.x, cr, ar0);  ai0 = fmaf(gv.x, ci, ai0);
        ar1 = fmaf(gv.y, cr, ar1);  ai1 = fmaf(gv.y, ci, ai1);
        ar2 = fmaf(gv.z, cr, ar2);  ai2 = fmaf(gv.z, ci, ai2);
        ar3 = fmaf(gv.w, cr, ar3);  ai3 = fmaf(gv.w, ci, ai3);
        const float nr = fmaf(cr, wr, -ci * wi);
        ci = fmaf(ci, wr, cr * wi);
        cr = nr;
    }

    // fractional-shift phase: e^{+i * 2*pi*frac*f/512} (shared across batches)
    {
        const float phi = 6.2831853071795864f * frac * (float)f * (1.0f / 512.0f);
        float sp, cp;
        sincosf(phi, &sp, &cp);
        const float arr[4] = {ar0, ar1, ar2, ar3};
        const float aii[4] = {ai0, ai1, ai2, ai3};
#pragma unroll
        for (int b = 0; b < NB; ++b) {
            const float re = fmaf(arr[b], cp, -aii[b] * sp);
            const float im = fmaf(arr[b], sp,  aii[b] * cp);
            const size_t o = ((size_t)b * NF + f) * NT + t;
            out[o]       = sqrtf(fmaf(re, re, im * im)) + 1.1920929e-7f;
            out[BFT + o] = re;
        }
    }

    // f = 256 (upper-half block only): sum_n u[n]*(-1)^n per batch.
    // Warp w<4 reduces batch w; n = lane+32k keeps lane parity = n parity.
    if (half == 1) {
        const int w = tid >> 5, lane = tid & 31;
        if (w < NB) {
            float s = 0.0f;
#pragma unroll
            for (int k = 0; k < 8; ++k) s += suv[0][lane + 32 * k][w];
            if (lane & 1) s = -s;
#pragma unroll
            for (int o = 16; o > 0; o >>= 1)
                s += __shfl_xor_sync(0xffffffffu, s, o);
            if (lane == 0) {
                const float phi = 3.1415926535897932f * frac;  // 2*pi*frac*256/512
                float sp, cp;
                sincosf(phi, &sp, &cp);
                const float re = s * cp;
                const float im = s * sp;
                const size_t o = ((size_t)w * NF + 256) * NT + t;
                out[o]       = sqrtf(fmaf(re, re, im * im)) + 1.1920929e-7f;
                out[BFT + o] = re;
            }
        }
    }
}

// ---------------------------------------------------------------------------
extern "C" void kernel_launch(void* const* d_in, const int* in_sizes, int n_in,
                              void* d_out, int out_size) {
    // x is the unique large input; win_length is the middle input under both
    // insertion and alphabetical order; strides is the remaining small one.
    int ix = 0;
    for (int i = 1; i < n_in; ++i)
        if (in_sizes[i] > in_sizes[ix]) ix = i;
    const float* x  = (const float*)d_in[ix];
    const float* wl = (const float*)d_in[1];
    const float* st = (const float*)d_in[(ix == 0) ? 2 : 0];
    float* out = (float*)d_out;

    prep_kernel<<<1, 256>>>(wl, st);

    dim3 grid(NT, 2);
    adstft_kernel<<<grid, 128>>>(x, out);
}

// round 6
// speedup vs baseline: 1.6684x; 1.2344x over previous
#include <cuda_runtime.h>

// Fixed problem shapes: B=4, L=80000, N=512, F=257, STRIDE=256 -> T=311
#define NB  4
#define NL  80000
#define NN  512
#define NF  257
#define NT  311
#define BFT (NB * NF * NT)   // 319708

#define TWO_PI 6.2831853071795864769f

// Padded float4 index: one float4 of pad every 32 entries kills the
// 16-way bank conflict on direct-phase sub-block bases (32*r).
__device__ __forceinline__ int PAD(int n) { return n + (n >> 5); }
__device__ __forceinline__ int bitrev4(int v) {
    return ((v & 1) << 3) | ((v & 2) << 1) | ((v & 4) >> 1) | ((v & 8) >> 3);
}

// ---------------------------------------------------------------------------
// One block per frame t. 256 threads. 4 batches ride in float4 lanes.
//  Phase 0: window + radix-2 DIF stage 0 fused (pairs (n, n+256), twiddle
//           w_512^n on the difference).
//  Stages 1..3: radix-2 DIF butterflies in shared memory -> 16 sub-blocks of
//           length 32; sub-block r holds the subproblem for f mod 16 ==
//           bitrev4(r).
//  Direct: thread f does the 32-point DFT of its sub-block with a register
//           twiddle rotation (step e^{-2*pi*i*(f>>4)/32}); f=256 is the q=16
//           case of the same path, run by thread 0.
// Output layout (established rounds 1-4):
//   floats [0, BFT)     : spec = |stft| + eps
//   floats [BFT, 2*BFT) : real(stft)
// ---------------------------------------------------------------------------
__global__ void __launch_bounds__(256)
adstft_kernel(const float* __restrict__ x,
              const float* __restrict__ wlp,
              const float* __restrict__ stp,
              float* __restrict__ out) {
    __shared__ float4 sre[528];
    __shared__ float4 sim[528];

    const int t   = blockIdx.x;
    const int tid = threadIdx.x;

    const float wl = fminf(fmaxf(wlp[0], 25.6f), 512.0f);   // WIN_MIN..WIN_MAX
    const float st = fminf(fmaxf(stp[0], 0.0f), 512.0f);    // STRIDE_MIN..MAX
    const float frame = st * (float)t;                       // == cumsum for integral st
    const float flo   = floorf(frame);
    const float frac  = frame - flo;
    const int   i0    = (int)flo;
    const float hi    = ceilf ((511.0f + wl) * 0.5f);
    const float lo    = floorf((511.0f - wl) * 0.5f);
    const float woff  = (wl - 511.0f) * 0.5f;

    // ---- Phase 0: window taps + fused DIF stage 0 ----
    float tap[2];
#pragma unroll
    for (int h = 0; h < 2; ++h) {
        const int n = tid + h * 256;
        const float base = (float)n - frac;
        float tp = 0.0f;
        if (!(base >= hi || base <= lo)) {
            float ang = TWO_PI * (base + woff) / wl;
            tp = (0.5f - 0.5f * __cosf(ang)) * 0.00390625f;   // / N * 2
        }
        tap[h] = tp;
    }
    float u[NB], v[NB];
#pragma unroll
    for (int b = 0; b < NB; ++b) {
        const float* xb = x + (size_t)b * NL;
        const int ia = i0 + tid, ib = i0 + tid + 256;
        const float ga = ((ia >= 0 && ia < NL) ? xb[ia] : 0.0f) * tap[0];
        const float gb = ((ib >= 0 && ib < NL) ? xb[ib] : 0.0f) * tap[1];
        u[b] = ga + gb;
        v[b] = ga - gb;
    }
    {
        float swi, swr;
        sincosf(-TWO_PI * (float)tid * (1.0f / 512.0f), &swi, &swr);
        sre[PAD(tid)]       = make_float4(u[0], u[1], u[2], u[3]);
        sim[PAD(tid)]       = make_float4(0.f, 0.f, 0.f, 0.f);
        sre[PAD(tid + 256)] = make_float4(v[0]*swr, v[1]*swr, v[2]*swr, v[3]*swr);
        sim[PAD(tid + 256)] = make_float4(v[0]*swi, v[1]*swi, v[2]*swi, v[3]*swi);
    }
    __syncthreads();

    // ---- Stages 1..3 ----
#pragma unroll
    for (int s = 1; s <= 3; ++s) {
        const int H   = 256 >> s;
        const int j   = tid & (H - 1);
        const int blk = tid >> (8 - s);
        const int p0  = (blk << (9 - s)) + j;
        const int p1  = p0 + H;
        float wi, wr;
        sincosf(-TWO_PI * (float)(j << s) * (1.0f / 512.0f), &wi, &wr);

        const float4 arN = sre[PAD(p0)], aiN = sim[PAD(p0)];
        const float4 brN = sre[PAD(p1)], biN = sim[PAD(p1)];
        float4 tre, tim, dre, dim, bre, bim;
        tre.x = arN.x + brN.x; tre.y = arN.y + brN.y; tre.z = arN.z + brN.z; tre.w = arN.w + brN.w;
        tim.x = aiN.x + biN.x; tim.y = aiN.y + biN.y; tim.z = aiN.z + biN.z; tim.w = aiN.w + biN.w;
        dre.x = arN.x - brN.x; dre.y = arN.y - brN.y; dre.z = arN.z - brN.z; dre.w = arN.w - brN.w;
        dim.x = aiN.x - biN.x; dim.y = aiN.y - biN.y; dim.z = aiN.z - biN.z; dim.w = aiN.w - biN.w;
        bre.x = fmaf(dre.x, wr, -dim.x * wi); bim.x = fmaf(dre.x, wi, dim.x * wr);
        bre.y = fmaf(dre.y, wr, -dim.y * wi); bim.y = fmaf(dre.y, wi, dim.y * wr);
        bre.z = fmaf(dre.z, wr, -dim.z * wi); bim.z = fmaf(dre.z, wi, dim.z * wr);
        bre.w = fmaf(dre.w, wr, -dim.w * wi); bim.w = fmaf(dre.w, wi, dim.w * wr);
        sre[PAD(p0)] = tre; sim[PAD(p0)] = tim;
        sre[PAD(p1)] = bre; sim[PAD(p1)] = bim;
        __syncthreads();
    }

    // ---- Direct 32-point DFT per frequency ----
#pragma unroll 1
    for (int f = tid; f < NF; f += 512) {   // tid 0 also does f = 256 (0+512? no)
        // loop trick below: see dispatch — tid does f=tid; tid==0 redoes f=256
        ;
    }
    // (explicit calls to keep codegen tight)
    {
        // helper as a lambda-free inline block, executed for f=tid and,
        // on thread 0, again for f=256
        for (int pass = 0; pass < 2; ++pass) {
            int f;
            if (pass == 0) f = tid;
            else { if (tid != 0) break; f = 256; }

            const int base = 33 * bitrev4(f & 15);   // PAD(32*r) = 33*r
            const int q    = f >> 4;
            float wi, wr;
            sincosf(-TWO_PI * (float)q * (1.0f / 32.0f), &wi, &wr);
            float cr = 1.0f, ci = 0.0f;
            float4 AR = make_float4(0.f, 0.f, 0.f, 0.f);
            float4 AI = make_float4(0.f, 0.f, 0.f, 0.f);
#pragma unroll 8
            for (int m = 0; m < 32; ++m) {
                const float4 yre = sre[base + m];
                const float4 yim = sim[base + m];
                const float nci = -ci;
                AR.x = fmaf(yre.x, cr, AR.x); AR.x = fmaf(yim.x, nci, AR.x);
                AI.x = fmaf(yre.x, ci, AI.x); AI.x = fmaf(yim.x, cr,  AI.x);
                AR.y = fmaf(yre.y, cr, AR.y); AR.y = fmaf(yim.y, nci, AR.y);
                AI.y = fmaf(yre.y, ci, AI.y); AI.y = fmaf(yim.y, cr,  AI.y);
                AR.z = fmaf(yre.z, cr, AR.z); AR.z = fmaf(yim.z, nci, AR.z);
                AI.z = fmaf(yre.z, ci, AI.z); AI.z = fmaf(yim.z, cr,  AI.z);
                AR.w = fmaf(yre.w, cr, AR.w); AR.w = fmaf(yim.w, nci, AR.w);
                AI.w = fmaf(yre.w, ci, AI.w); AI.w = fmaf(yim.w, cr,  AI.w);
                const float nr = fmaf(cr, wr, -ci * wi);
                ci = fmaf(ci, wr, cr * wi);
                cr = nr;
            }

            // fractional-shift phase: e^{+i * 2*pi*frac*f/512}
            float sp, cp;
            sincosf(TWO_PI * frac * (float)f * (1.0f / 512.0f), &sp, &cp);
            const float arr[4] = {AR.x, AR.y, AR.z, AR.w};
            const float aii[4] = {AI.x, AI.y, AI.z, AI.w};
#pragma unroll
            for (int b = 0; b < NB; ++b) {
                const float re = fmaf(arr[b], cp, -aii[b] * sp);
                const float im = fmaf(arr[b], sp,  aii[b] * cp);
                const size_t o = ((size_t)b * NF + f) * NT + t;
                out[o]       = sqrtf(fmaf(re, re, im * im)) + 1.1920929e-7f;
                out[BFT + o] = re;
            }
        }
    }
}

// ---------------------------------------------------------------------------
extern "C" void kernel_launch(void* const* d_in, const int* in_sizes, int n_in,
                              void* d_out, int out_size) {
    // x is the unique large input; win_length is the middle input under both
    // insertion and alphabetical order; strides is the remaining small one.
    int ix = 0;
    for (int i = 1; i < n_in; ++i)
        if (in_sizes[i] > in_sizes[ix]) ix = i;
    const float* x  = (const float*)d_in[ix];
    const float* wl = (const float*)d_in[1];
    const float* st = (const float*)d_in[(ix == 0) ? 2 : 0];
    float* out = (float*)d_out;

    adstft_kernel<<<NT, 256>>>(x, wl, st, out);
}

// round 7
// speedup vs baseline: 2.1403x; 1.2829x over previous
#include <cuda_runtime.h>

// Fixed problem shapes: B=4, L=80000, N=512, F=257, STRIDE=256 -> T=311
#define NB  4
#define NL  80000
#define NN  512
#define NF  257
#define NT  311
#define BFT (NB * NF * NT)   // 319708

#define TWO_PI 6.2831853071795864769f

// Pad one float every 32: kills bank conflicts on stage strides and makes
// direct-phase sub-block bases (32*r -> 33*r) conflict-free.
__device__ __forceinline__ int PAD(int n) { return n + (n >> 5); }
__device__ __forceinline__ int bitrev4(int v) {
    return ((v & 1) << 3) | ((v & 2) << 1) | ((v & 4) >> 1) | ((v & 8) >> 3);
}

// ---------------------------------------------------------------------------
// One block per (frame t, batch b). 256 threads, scalar lanes.
//  Phase 0: window + fused radix-2 DIF stage 0 (pairs (n, n+256), twiddle
//           w_512^n on the difference).
//  Stages 1..3: radix-2 DIF butterflies in shared -> 16 sub-blocks of 32;
//           sub-block r serves frequencies with f mod 16 == bitrev4(r).
//  Direct: thread f runs the 32-point DFT of its sub-block with a register
//           rotation (step e^{-2*pi*i*(f>>4)/32}); f=256 is the q=16 case,
//           second pass on thread 0.
// Output layout (established rounds 1-4):
//   floats [0, BFT)     : spec = |stft| + eps
//   floats [BFT, 2*BFT) : real(stft)
// ---------------------------------------------------------------------------
__global__ void __launch_bounds__(256, 8)
adstft_kernel(const float* __restrict__ x,
              const float* __restrict__ wlp,
              const float* __restrict__ stp,
              float* __restrict__ out) {
    __shared__ float sre[528];
    __shared__ float sim[528];

    const int t   = blockIdx.x;
    const int b   = blockIdx.y;
    const int tid = threadIdx.x;

    const float wl = fminf(fmaxf(wlp[0], 25.6f), 512.0f);   // WIN_MIN..WIN_MAX
    const float st = fminf(fmaxf(stp[0], 0.0f), 512.0f);    // STRIDE_MIN..MAX
    const float frame = st * (float)t;                       // == cumsum for integral st
    const float flo   = floorf(frame);
    const float frac  = frame - flo;
    const int   i0    = (int)flo;
    const float hi    = ceilf ((511.0f + wl) * 0.5f);
    const float lo    = floorf((511.0f - wl) * 0.5f);
    const float woff  = (wl - 511.0f) * 0.5f;

    // ---- Phase 0: window taps + fused DIF stage 0 ----
    float tap0, tap1;
    {
        const float base0 = (float)tid - frac;
        const float base1 = (float)(tid + 256) - frac;
        tap0 = 0.0f; tap1 = 0.0f;
        if (!(base0 >= hi || base0 <= lo))
            tap0 = (0.5f - 0.5f * __cosf(TWO_PI * (base0 + woff) / wl)) * 0.00390625f;
        if (!(base1 >= hi || base1 <= lo))
            tap1 = (0.5f - 0.5f * __cosf(TWO_PI * (base1 + woff) / wl)) * 0.00390625f;
    }
    {
        const float* xb = x + (size_t)b * NL;
        const int ia = i0 + tid, ib = i0 + tid + 256;
        const float ga = ((ia >= 0 && ia < NL) ? xb[ia] : 0.0f) * tap0;
        const float gb = ((ib >= 0 && ib < NL) ? xb[ib] : 0.0f) * tap1;
        const float u = ga + gb;
        const float v = ga - gb;
        float swi, swr;
        __sincosf(-TWO_PI * (float)tid * (1.0f / 512.0f), &swi, &swr);
        sre[PAD(tid)]       = u;
        sim[PAD(tid)]       = 0.0f;
        sre[PAD(tid + 256)] = v * swr;
        sim[PAD(tid + 256)] = v * swi;
    }
    __syncthreads();

    // ---- Stages 1..3 ----
#pragma unroll
    for (int s = 1; s <= 3; ++s) {
        const int H   = 256 >> s;
        const int j   = tid & (H - 1);
        const int blk = tid >> (8 - s);
        const int p0  = (blk << (9 - s)) + j;
        const int p1  = p0 + H;
        float wi, wr;
        __sincosf(-TWO_PI * (float)(j << s) * (1.0f / 512.0f), &wi, &wr);

        const float ar = sre[PAD(p0)], ai = sim[PAD(p0)];
        const float br = sre[PAD(p1)], bi = sim[PAD(p1)];
        const float dr = ar - br, di = ai - bi;
        sre[PAD(p0)] = ar + br;
        sim[PAD(p0)] = ai + bi;
        sre[PAD(p1)] = fmaf(dr, wr, -di * wi);
        sim[PAD(p1)] = fmaf(dr, wi,  di * wr);
        __syncthreads();
    }

    // ---- Direct 32-point DFT per frequency ----
    for (int pass = 0; pass < 2; ++pass) {
        int f;
        if (pass == 0) f = tid;
        else { if (tid != 0) break; f = 256; }

        const int base = 33 * bitrev4(f & 15);   // PAD(32*r) = 33*r
        const int q    = f >> 4;
        float wi, wr;
        __sincosf(-TWO_PI * (float)q * (1.0f / 32.0f), &wi, &wr);
        float cr = 1.0f, ci = 0.0f;
        float ar = 0.0f, ai = 0.0f;
#pragma unroll 8
        for (int m = 0; m < 32; ++m) {
            const float yre = sre[base + m];
            const float yim = sim[base + m];
            ar = fmaf(yre, cr, ar);  ar = fmaf(yim, -ci, ar);
            ai = fmaf(yre, ci, ai);  ai = fmaf(yim,  cr, ai);
            const float nr = fmaf(cr, wr, -ci * wi);
            ci = fmaf(ci, wr, cr * wi);
            cr = nr;
        }

        // fractional-shift phase: e^{+i * 2*pi*frac*f/512}
        float sp, cp;
        __sincosf(TWO_PI * frac * (float)f * (1.0f / 512.0f), &sp, &cp);
        const float re = fmaf(ar, cp, -ai * sp);
        const float im = fmaf(ar, sp,  ai * cp);

        const size_t o = ((size_t)b * NF + f) * NT + t;
        out[o]       = sqrtf(fmaf(re, re, im * im)) + 1.1920929e-7f;  // spec
        out[BFT + o] = re;                                            // real(stft)
    }
}

// ---------------------------------------------------------------------------
extern "C" void kernel_launch(void* const* d_in, const int* in_sizes, int n_in,
                              void* d_out, int out_size) {
    // x is the unique large input; win_length is the middle input under both
    // insertion and alphabetical order; strides is the remaining small one.
    int ix = 0;
    for (int i = 1; i < n_in; ++i)
        if (in_sizes[i] > in_sizes[ix]) ix = i;
    const float* x  = (const float*)d_in[ix];
    const float* wl = (const float*)d_in[1];
    const float* st = (const float*)d_in[(ix == 0) ? 2 : 0];
    float* out = (float*)d_out;

    dim3 grid(NT, NB);
    adstft_kernel<<<grid, 256>>>(x, wl, st, out);
}

// round 8
// speedup vs baseline: 2.4961x; 1.1662x over previous
#include <cuda_runtime.h>

// Fixed problem shapes: B=4, L=80000, N=512, F=257, STRIDE=256 -> T=311
#define NB  4
#define NL  80000
#define NN  512
#define NF  257
#define NT  311
#define BFT (NB * NF * NT)   // 319708

#define TWO_PI 6.2831853071795864769f

// Pad one float every 32: conflict-free smem stage strides and gathers.
__device__ __forceinline__ int PAD(int n) { return n + (n >> 5); }

// ---------------------------------------------------------------------------
// One block per (frame t, batch b). 256 threads = 8 warps.
//  Phase 0: window + fused radix-2 DIF stage H=256.
//  Stages H=128,64,32: radix-2 DIF butterflies in shared (3 barriers).
//  Warp phase: after H=32, sub-problems are contiguous 32-blocks. Warp w
//    takes sub-blocks r=2w and r=2w+1 (one complex value per lane each) and
//    runs stages H=16,8,4,2,1 with shfl-xor butterflies — no barriers.
//  Output: position n=32r+l holds frequency f=16*bitrev5(l)+bitrev4(r);
//    each thread emits its (up to 2) outputs with f<=256.
// Output layout (established rounds 1-4):
//   floats [0, BFT)     : spec = |stft| + eps
//   floats [BFT, 2*BFT) : real(stft)
// ---------------------------------------------------------------------------
__global__ void __launch_bounds__(256, 8)
adstft_kernel(const float* __restrict__ x,
              const float* __restrict__ wlp,
              const float* __restrict__ stp,
              float* __restrict__ out) {
    __shared__ float sre[528];
    __shared__ float sim[528];

    const int t   = blockIdx.x;
    const int b   = blockIdx.y;
    const int tid = threadIdx.x;

    const float wl = fminf(fmaxf(wlp[0], 25.6f), 512.0f);   // WIN_MIN..WIN_MAX
    const float st = fminf(fmaxf(stp[0], 0.0f), 512.0f);    // STRIDE_MIN..MAX
    const float frame = st * (float)t;                       // == cumsum for integral st
    const float flo   = floorf(frame);
    const float frac  = frame - flo;
    const int   i0    = (int)flo;
    const float hi    = ceilf ((511.0f + wl) * 0.5f);
    const float lo    = floorf((511.0f - wl) * 0.5f);
    const float woff  = (wl - 511.0f) * 0.5f;

    // ---- Phase 0: window taps + fused DIF stage H=256 ----
    float tap0, tap1;
    {
        const float base0 = (float)tid - frac;
        const float base1 = (float)(tid + 256) - frac;
        tap0 = 0.0f; tap1 = 0.0f;
        if (!(base0 >= hi || base0 <= lo))
            tap0 = (0.5f - 0.5f * __cosf(TWO_PI * (base0 + woff) / wl)) * 0.00390625f;
        if (!(base1 >= hi || base1 <= lo))
            tap1 = (0.5f - 0.5f * __cosf(TWO_PI * (base1 + woff) / wl)) * 0.00390625f;
    }
    {
        const float* xb = x + (size_t)b * NL;
        const int ia = i0 + tid, ib = i0 + tid + 256;
        const float ga = ((ia >= 0 && ia < NL) ? xb[ia] : 0.0f) * tap0;
        const float gb = ((ib >= 0 && ib < NL) ? xb[ib] : 0.0f) * tap1;
        const float u = ga + gb;
        const float v = ga - gb;
        float swi, swr;
        __sincosf(-TWO_PI * (float)tid * (1.0f / 512.0f), &swi, &swr);
        sre[PAD(tid)]       = u;
        sim[PAD(tid)]       = 0.0f;
        sre[PAD(tid + 256)] = v * swr;
        sim[PAD(tid + 256)] = v * swi;
    }
    __syncthreads();

    // ---- Stages H=128, 64, 32 in shared ----
#pragma unroll
    for (int s = 1; s <= 3; ++s) {
        const int H   = 256 >> s;
        const int j   = tid & (H - 1);
        const int blk = tid >> (8 - s);
        const int p0  = (blk << (9 - s)) + j;
        const int p1  = p0 + H;
        float wi, wr;
        __sincosf(-TWO_PI * (float)(j << s) * (1.0f / 512.0f), &wi, &wr);

        const float ar = sre[PAD(p0)], ai = sim[PAD(p0)];
        const float br = sre[PAD(p1)], bi = sim[PAD(p1)];
        const float dr = ar - br, di = ai - bi;
        sre[PAD(p0)] = ar + br;
        sim[PAD(p0)] = ai + bi;
        sre[PAD(p1)] = fmaf(dr, wr, -di * wi);
        sim[PAD(p1)] = fmaf(dr, wi,  di * wr);
        __syncthreads();
    }

    // ---- Warp-local stages H=16..1 on two 32-point sub-blocks ----
    const int w = tid >> 5;
    const int l = tid & 31;
    const int g0 = 64 * w + l;          // sub-block r = 2w, local pos l
    float zr0 = sre[PAD(g0)],      zi0 = sim[PAD(g0)];
    float zr1 = sre[PAD(g0 + 32)], zi1 = sim[PAD(g0 + 32)];   // r = 2w+1

#pragma unroll
    for (int H = 16; H >= 1; H >>= 1) {
        const int step = 16 / H;        // = 32/(2H)
        float twi, twr;
        __sincosf(-TWO_PI * (float)(step * (l & (H - 1))) * (1.0f / 32.0f),
                  &twi, &twr);
        const bool bot = (l & H) != 0;

        float pr = __shfl_xor_sync(0xffffffffu, zr0, H);
        float pi = __shfl_xor_sync(0xffffffffu, zi0, H);
        float dr = pr - zr0, di = pi - zi0;              // a - b (partner is a)
        float tr = fmaf(dr, twr, -di * twi);
        float ti = fmaf(dr, twi,  di * twr);
        zr0 = bot ? tr : (zr0 + pr);
        zi0 = bot ? ti : (zi0 + pi);

        pr = __shfl_xor_sync(0xffffffffu, zr1, H);
        pi = __shfl_xor_sync(0xffffffffu, zi1, H);
        dr = pr - zr1; di = pi - zi1;
        tr = fmaf(dr, twr, -di * twi);
        ti = fmaf(dr, twi,  di * twr);
        zr1 = bot ? tr : (zr1 + pr);
        zi1 = bot ? ti : (zi1 + pi);
    }

    // ---- Emit: f = 16*bitrev5(l) + bitrev4(r) ----
    const int q5 = ((l & 1) << 4) | ((l & 2) << 2) | (l & 4)
                 | ((l & 8) >> 2) | ((l & 16) >> 4);            // bitrev5(l)
    const int r3 = ((w & 1) << 2) | (w & 2) | ((w & 4) >> 2);   // bitrev3(w)
    const int f0 = (q5 << 4) | r3;        // sub-block 2w
    const int f1 = f0 | 8;                // sub-block 2w+1

    if (f0 <= 256) {
        float sp, cp;
        __sincosf(TWO_PI * frac * (float)f0 * (1.0f / 512.0f), &sp, &cp);
        const float re = fmaf(zr0, cp, -zi0 * sp);
        const float im = fmaf(zr0, sp,  zi0 * cp);
        const size_t o = ((size_t)b * NF + f0) * NT + t;
        out[o]       = sqrtf(fmaf(re, re, im * im)) + 1.1920929e-7f;
        out[BFT + o] = re;
    }
    if (f1 <= 256) {
        float sp, cp;
        __sincosf(TWO_PI * frac * (float)f1 * (1.0f / 512.0f), &sp, &cp);
        const float re = fmaf(zr1, cp, -zi1 * sp);
        const float im = fmaf(zr1, sp,  zi1 * cp);
        const size_t o = ((size_t)b * NF + f1) * NT + t;
        out[o]       = sqrtf(fmaf(re, re, im * im)) + 1.1920929e-7f;
        out[BFT + o] = re;
    }
}

// ---------------------------------------------------------------------------
extern "C" void kernel_launch(void* const* d_in, const int* in_sizes, int n_in,
                              void* d_out, int out_size) {
    // x is the unique large input; win_length is the middle input under both
    // insertion and alphabetical order; strides is the remaining small one.
    int ix = 0;
    for (int i = 1; i < n_in; ++i)
        if (in_sizes[i] > in_sizes[ix]) ix = i;
    const float* x  = (const float*)d_in[ix];
    const float* wl = (const float*)d_in[1];
    const float* st = (const float*)d_in[(ix == 0) ? 2 : 0];
    float* out = (float*)d_out;

    dim3 grid(NT, NB);
    adstft_kernel<<<grid, 256>>>(x, wl, st, out);
}